// round 16
// baseline (speedup 1.0000x reference)
#include <cuda_runtime.h>

// DendriticLayer: B=512, N_IN=1024, N_OUT=256, T=100, dt=1.
// Event-scatter formulation (R9 = best):
//   delta[ceil(s_j)] += 0.1*K2*w_j*exp((s_j-ceil(s_j))/5)   (private SMEM col)
//   Chat_t = d*Chat_{t-1} + delta_t ;  w_t = 0.9*w_{t-1} + Chat_t  (w = K2*v)
//   e_t = exp2(w_t);  out = (sum t*e_t)/(sum e_t)
// R16 = R9 byte-identical arithmetic, block size 128 -> 64 (grid 2048):
// same warps/SM in flight, but last-wave imbalance 7/6 -> 14/13 and shorter
// per-block ramp. Table is [13][64] float4 = 13.3KB/block.

#define CH0 13   // phase-0: 52 steps (t in [0,52))
#define CH1 12   // phase-1: 48 steps (t in [52,100))
#define BT  64   // block threads

__device__ __forceinline__ float ex2(float x) {
    float y;
    asm("ex2.approx.ftz.f32 %0, %1;" : "=f"(y) : "f"(x));
    return y;
}

constexpr float D1f = 0.81873075307798185867f;  // exp(-0.2)
constexpr float K2f = 2.8853900817779268147f;   // 2*log2(e)

struct Acc { float C, w, S, WS; };

__device__ __forceinline__ void step(Acc& a, float dlt, float tf) {
    a.C = fmaf(a.C, D1f, dlt);    // FFMA-imm
    a.w = fmaf(a.w, 0.9f, a.C);   // FFMA-imm
    const float e = ex2(a.w);     // MUFU.EX2
    a.S += e;                     // FADD
    a.WS = fmaf(e, tf, a.WS);     // FFMA-imm
}

template <int T0, int NCH, int K>
__device__ __forceinline__ void run(Acc& a, const float4* __restrict__ col) {
    if constexpr (K < NCH) {
        const float4 d4 = col[K * BT];           // LDS.128: 4 steps of deltas
        step(a, d4.x, (float)(T0 + 4 * K + 0));
        step(a, d4.y, (float)(T0 + 4 * K + 1));
        step(a, d4.z, (float)(T0 + 4 * K + 2));
        step(a, d4.w, (float)(T0 + 4 * K + 3));
        run<T0, NCH, K + 1>(a, col);
    }
}

__global__ __launch_bounds__(BT)
void dendritic_kernel(const float* __restrict__ spikes,  // [512,1024]
                      const float* __restrict__ W,       // [256,1024]
                      float* __restrict__ out)           // [512,256]
{
    __shared__ float4 tbl[CH0][BT];              // 13.3KB

    const int tid = threadIdx.x;
    const int idx = blockIdx.x * BT + tid;       // b*256 + o
    const int o   = idx & 255;

    const float4 s4 = reinterpret_cast<const float4*>(spikes)[idx];
    const float4 w4 = reinterpret_cast<const float4*>(W)[257 * o];

    const float e0 = ceilf(s4.x), e1 = ceilf(s4.y), e2 = ceilf(s4.z), e3 = ceilf(s4.w);
    const float kk = 0.1f * K2f;
    const float c0 = kk * w4.x * __expf(0.2f * (s4.x - e0));
    const float c1 = kk * w4.y * __expf(0.2f * (s4.y - e1));
    const float c2 = kk * w4.z * __expf(0.2f * (s4.z - e2));
    const float c3 = kk * w4.w * __expf(0.2f * (s4.w - e3));
    const int i0 = (int)e0, i1 = (int)e1, i2 = (int)e2, i3 = (int)e3;

    float* tf = reinterpret_cast<float*>(tbl);
    const int tb = tid * 4;
    // scalar slot for timestep k (local to a phase): (k>>2)*(BT*4) + tid*4 + (k&3)
    #define SLOT(k) (((k) >> 2) * (BT * 4) + tb + ((k) & 3))

    const float4* col = &tbl[0][tid];
    float4 z4 = make_float4(0.f, 0.f, 0.f, 0.f);
    Acc a; a.C = 0.f; a.w = 0.f; a.S = 0.f; a.WS = 0.f;

    // ---- phase 0: t in [0,52) ----
    #pragma unroll
    for (int c = 0; c < CH0; ++c) tbl[c][tid] = z4;       // 13x STS.128
    if (i0 < 52) tf[SLOT(i0)] += c0;                       // private RMW, race-free
    if (i1 < 52) tf[SLOT(i1)] += c1;
    if (i2 < 52) tf[SLOT(i2)] += c2;
    if (i3 < 52) tf[SLOT(i3)] += c3;
    run<0, CH0, 0>(a, col);

    // ---- phase 1: t in [52,100) ----
    #pragma unroll
    for (int c = 0; c < CH1; ++c) tbl[c][tid] = z4;       // 12x STS.128
    const int j0 = i0 - 52, j1 = i1 - 52, j2 = i2 - 52, j3 = i3 - 52;
    if ((unsigned)j0 < 48u) tf[SLOT(j0)] += c0;
    if ((unsigned)j1 < 48u) tf[SLOT(j1)] += c1;
    if ((unsigned)j2 < 48u) tf[SLOT(j2)] += c2;
    if ((unsigned)j3 < 48u) tf[SLOT(j3)] += c3;
    run<52, CH1, 0>(a, col);

    out[idx] = a.WS / a.S;
}

extern "C" void kernel_launch(void* const* d_in, const int* in_sizes, int n_in,
                              void* d_out, int out_size)
{
    const float* spikes = (const float*)d_in[0];  // [512*1024]
    const float* W      = (const float*)d_in[1];  // [256*1024]
    float* out          = (float*)d_out;          // [512*256]

    dendritic_kernel<<<2048, BT>>>(spikes, W, out);
}

// round 17
// speedup vs baseline: 1.1661x; 1.1661x over previous
#include <cuda_runtime.h>

// DendriticLayer: B=512, N_IN=1024, N_OUT=256, T=100, dt=1.
// CONN block-diagonal (4 inputs/output) -> per-(b,o) scalar recurrence.
//
// Event-scatter formulation (R9 = measured optimum across 16 rounds):
//   delta[ceil(s_j)] += 0.1*K2*w_j*exp((s_j-ceil(s_j))/5)   (private SMEM col)
//   Chat_t = d*Chat_{t-1} + delta_t ;  w_t = 0.9*w_{t-1} + Chat_t  (w = K2*v)
//   e_t = exp2(w_t);  out = (sum t*e_t)/(sum e_t)
// Table: float4 tbl[chunk][tid] -> one LDS.128 serves 4 timesteps,
// conflict-free; columns thread-private (no atomics, no syncs).
// Two phases (52+48 steps), 26.6KB/block, 1024 blocks = single wave.
// Body = 5 instrs/step (structural floor for this recurrence) + 0.25 LDS.

#define CH0 13   // phase-0: 52 steps (t in [0,52))
#define CH1 12   // phase-1: 48 steps (t in [52,100))

__device__ __forceinline__ float ex2(float x) {
    float y;
    asm("ex2.approx.ftz.f32 %0, %1;" : "=f"(y) : "f"(x));
    return y;
}

constexpr float D1f = 0.81873075307798185867f;  // exp(-0.2)
constexpr float K2f = 2.8853900817779268147f;   // 2*log2(e)

struct Acc { float C, w, S, WS; };

__device__ __forceinline__ void step(Acc& a, float dlt, float tf) {
    a.C = fmaf(a.C, D1f, dlt);    // FFMA-imm
    a.w = fmaf(a.w, 0.9f, a.C);   // FFMA-imm
    const float e = ex2(a.w);     // MUFU.EX2
    a.S += e;                     // FADD
    a.WS = fmaf(e, tf, a.WS);     // FFMA-imm
}

template <int T0, int NCH, int K>
__device__ __forceinline__ void run(Acc& a, const float4* __restrict__ col) {
    if constexpr (K < NCH) {
        const float4 d4 = col[K * 128];          // LDS.128: 4 steps of deltas
        step(a, d4.x, (float)(T0 + 4 * K + 0));
        step(a, d4.y, (float)(T0 + 4 * K + 1));
        step(a, d4.z, (float)(T0 + 4 * K + 2));
        step(a, d4.w, (float)(T0 + 4 * K + 3));
        run<T0, NCH, K + 1>(a, col);
    }
}

__global__ __launch_bounds__(128)
void dendritic_kernel(const float* __restrict__ spikes,  // [512,1024]
                      const float* __restrict__ W,       // [256,1024]
                      float* __restrict__ out)           // [512,256]
{
    __shared__ float4 tbl[CH0][128];             // 26.6KB

    const int tid = threadIdx.x;
    const int idx = blockIdx.x * 128 + tid;      // b*256 + o
    const int o   = idx & 255;

    // spikes[b*1024 + 4o..4o+3] -> float4 index = idx (coalesced)
    const float4 s4 = reinterpret_cast<const float4*>(spikes)[idx];
    // W[o*1024 + 4o..4o+3] -> float4 index 257*o (L1-resident)
    const float4 w4 = reinterpret_cast<const float4*>(W)[257 * o];

    const float e0 = ceilf(s4.x), e1 = ceilf(s4.y), e2 = ceilf(s4.z), e3 = ceilf(s4.w);
    const float kk = 0.1f * K2f;
    const float c0 = kk * w4.x * __expf(0.2f * (s4.x - e0));
    const float c1 = kk * w4.y * __expf(0.2f * (s4.y - e1));
    const float c2 = kk * w4.z * __expf(0.2f * (s4.z - e2));
    const float c3 = kk * w4.w * __expf(0.2f * (s4.w - e3));
    const int i0 = (int)e0, i1 = (int)e1, i2 = (int)e2, i3 = (int)e3;

    float* tf = reinterpret_cast<float*>(tbl);
    const int tb = tid * 4;
    // scalar slot for timestep k (local to a phase): (k>>2)*512 + tid*4 + (k&3)
    #define SLOT(k) (((k) >> 2) * 512 + tb + ((k) & 3))

    const float4* col = &tbl[0][tid];
    float4 z4 = make_float4(0.f, 0.f, 0.f, 0.f);
    Acc a; a.C = 0.f; a.w = 0.f; a.S = 0.f; a.WS = 0.f;

    // ---- phase 0: t in [0,52) ----
    #pragma unroll
    for (int c = 0; c < CH0; ++c) tbl[c][tid] = z4;       // 13x STS.128
    if (i0 < 52) tf[SLOT(i0)] += c0;                       // private RMW, race-free
    if (i1 < 52) tf[SLOT(i1)] += c1;
    if (i2 < 52) tf[SLOT(i2)] += c2;
    if (i3 < 52) tf[SLOT(i3)] += c3;
    run<0, CH0, 0>(a, col);

    // ---- phase 1: t in [52,100) ----
    #pragma unroll
    for (int c = 0; c < CH1; ++c) tbl[c][tid] = z4;       // 12x STS.128
    const int j0 = i0 - 52, j1 = i1 - 52, j2 = i2 - 52, j3 = i3 - 52;
    if ((unsigned)j0 < 48u) tf[SLOT(j0)] += c0;            // single-compare guard
    if ((unsigned)j1 < 48u) tf[SLOT(j1)] += c1;
    if ((unsigned)j2 < 48u) tf[SLOT(j2)] += c2;
    if ((unsigned)j3 < 48u) tf[SLOT(j3)] += c3;
    run<52, CH1, 0>(a, col);

    out[idx] = a.WS / a.S;
}

extern "C" void kernel_launch(void* const* d_in, const int* in_sizes, int n_in,
                              void* d_out, int out_size)
{
    const float* spikes = (const float*)d_in[0];  // [512*1024]
    const float* W      = (const float*)d_in[1];  // [256*1024]
    float* out          = (float*)d_out;          // [512*256]

    dendritic_kernel<<<1024, 128>>>(spikes, W, out);
}